// round 2
// baseline (speedup 1.0000x reference)
#include <cuda_runtime.h>
#include <stdint.h>

#define BB 64
#define TT 256
#define NN 64
#define NPAIRS 2016              // 64*63/2
#define WG_PER_T 63              // 2016/32 words of samples per t
#define NWORDS (TT * WG_PER_T)   // 16128 total 32-sample words per column
#define WCHUNK 126               // words per phase-2 block
#define NBLK2 (NWORDS / WCHUNK)  // 128 blocks

// Bit matrix: bit s of g_bits[w][i] = (x[a,t,i] > x[b,t,i]) for sample (t, pair p),
// where w = t*63 + p/32, s = p%32. Layout word-major for coalesced access.
__device__ uint32_t g_bits[NWORDS][NN];   // ~4.1 MB
__device__ int g_H[NN * NN];              // Hamming accumulators (only i<j used)

// Build (a,b) pair table, packed a | (b<<8), into shared memory.
__device__ __forceinline__ void build_pairs(uint16_t* pr, int tid, int nthreads) {
    for (int p = tid; p < NPAIRS; p += nthreads) {
        int a = 0, off = 0;
        while (off + (BB - 1 - a) <= p) { off += (BB - 1 - a); a++; }
        int b = a + 1 + (p - off);
        pr[p] = (uint16_t)(a | (b << 8));
    }
}

// ---------------- Phase 1: sign-bit packing ----------------
// One block per t. Loads the 64x64 slab, enumerates 2016 pairs in groups of 32,
// packs comparison bits per column into 32-bit words.
__global__ __launch_bounds__(512) void phase1(const float* __restrict__ in) {
    __shared__ float xs[BB][NN];        // 16 KB, lane reads column -> conflict-free
    __shared__ uint16_t pr[NPAIRS];     // 4 KB
    int tid = threadIdx.x;
    int t = blockIdx.x;

    if (blockIdx.x == 0) {              // zero H for phase 2 atomics
        for (int k = tid; k < NN * NN; k += blockDim.x) g_H[k] = 0;
    }
    for (int idx = tid; idx < BB * NN; idx += blockDim.x) {
        int b = idx >> 6, i = idx & 63;
        xs[b][i] = in[b * (TT * NN) + t * NN + i];
    }
    build_pairs(pr, tid, blockDim.x);
    __syncthreads();

    int warp = tid >> 5, lane = tid & 31;
    int nwarps = blockDim.x >> 5;
    for (int task = warp; task < WG_PER_T * 2; task += nwarps) {
        int wg = task >> 1;             // which 32-sample group
        int col = ((task & 1) << 5) + lane;
        uint32_t word = 0;
        #pragma unroll
        for (int s = 0; s < 32; s++) {
            int p = (wg << 5) + s;
            uint16_t ab = pr[p];        // broadcast LDS
            int a = ab & 0xFF, b = ab >> 8;
            word |= (xs[a][col] > xs[b][col]) ? (1u << s) : 0u;
        }
        g_bits[t * WG_PER_T + wg][col] = word;  // coalesced 128B store
    }
}

// ---------------- Phase 2: XOR + popcount Gram ----------------
// Each block owns a 126-word chunk of samples for all 64 columns (32.25 KB tile),
// computes partial Hamming distances for all 2016 (i<j) pairs, atomically adds.
__global__ __launch_bounds__(512) void phase2() {
    __shared__ uint32_t tile[WCHUNK * NN];  // 32.25 KB
    __shared__ uint16_t pr[NPAIRS];
    int tid = threadIdx.x;

    const uint32_t* src = &g_bits[blockIdx.x * WCHUNK][0];  // contiguous chunk
    for (int idx = tid; idx < WCHUNK * NN; idx += blockDim.x) tile[idx] = src[idx];
    build_pairs(pr, tid, blockDim.x);
    __syncthreads();

    for (int p = tid; p < NPAIRS; p += blockDim.x) {
        uint16_t ab = pr[p];
        int i = ab & 0xFF, j = ab >> 8;
        int acc = 0;
        #pragma unroll 7
        for (int w = 0; w < WCHUNK; w++)
            acc += __popc(tile[w * NN + i] ^ tile[w * NN + j]);
        atomicAdd(&g_H[i * NN + j], acc);
    }
}

// ---------------- Phase 3: distance + broadcast ----------------
// D[i,j] = 1 - C/2016, C = 2K - 4H (K = 516096 unordered samples), diag = 0.
__global__ __launch_bounds__(256) void phase3(float* __restrict__ out) {
    __shared__ float D[NN * NN];
    int tid = threadIdx.x;
    for (int k = tid; k < NN * NN; k += blockDim.x) {
        int i = k >> 6, j = k & 63;
        float d = 0.0f;
        if (i != j) {
            int h = (i < j) ? g_H[i * NN + j] : g_H[j * NN + i];
            float C = 1032192.0f - 4.0f * (float)h;   // 2*516096 - 4H, exact in fp32
            d = 1.0f - C * (1.0f / 2016.0f);
        }
        D[k] = d;
    }
    __syncthreads();
    float* o = out + blockIdx.x * (NN * NN);
    for (int k = tid; k < NN * NN; k += blockDim.x) o[k] = D[k];
}

extern "C" void kernel_launch(void* const* d_in, const int* in_sizes, int n_in,
                              void* d_out, int out_size) {
    (void)in_sizes; (void)n_in; (void)out_size;
    const float* in = (const float*)d_in[0];
    float* out = (float*)d_out;

    phase1<<<TT, 512>>>(in);
    phase2<<<NBLK2, 512>>>();
    phase3<<<BB, 256>>>(out);
}

// round 3
// speedup vs baseline: 1.0707x; 1.0707x over previous
#include <cuda_runtime.h>
#include <stdint.h>

#define BB 64
#define TT 256
#define NN 64
#define NPAIRS 2016               // 64*63/2 batch pairs
#define WG_PER_T 63               // 32-pair words per t
#define XPAD 68                   // padded row stride (floats) for xs
#define ROWB (XPAD * 4)           // 272 bytes per xs row

__device__ int g_H[NN * NN];      // Hamming accumulators (only i<j used)

// ---------------- zero H ----------------
__global__ __launch_bounds__(512) void zeroH() {
    for (int k = threadIdx.x; k < NN * NN; k += 512) g_H[k] = 0;
}

// ---------------- fused: sign-bit pack + XOR/popcount Gram, one block per t ----
__global__ __launch_bounds__(512) void fusedKD(const float* __restrict__ in) {
    __shared__ __align__(16) float xs[BB][XPAD];          // 17.4 KB padded slab
    __shared__ __align__(16) uint32_t bits[WG_PER_T][NN]; // 16.1 KB bit matrix
    __shared__ uint32_t pr[NPAIRS];                       // 8.1 KB byte-offset pairs
    int tid = threadIdx.x;
    int t = blockIdx.x;

    // Load 64x64 slab (float4, coalesced) into padded smem rows.
    {
        const float4* src = (const float4*)in;
        for (int q = tid; q < BB * 16; q += 512) {
            int b = q >> 4, c = q & 15;
            float4 v = src[(size_t)b * (TT * 16) + t * 16 + c];
            *(float4*)&xs[b][c * 4] = v;
        }
    }
    // Pair table: pr[p] = (a*272) | ((b*272) << 16), closed-form decode + fixup.
    for (int p = tid; p < NPAIRS; p += 512) {
        int a = (int)floorf(63.5f - sqrtf(4032.25f - 2.0f * (float)p));
        if (a < 0) a = 0; if (a > 62) a = 62;
        int cum = 63 * a - ((a * (a - 1)) >> 1);
        if (p < cum)               { a--; cum = 63 * a - ((a * (a - 1)) >> 1); }
        else if (p >= cum + 63 - a){ a++; cum = 63 * a - ((a * (a - 1)) >> 1); }
        int b = a + 1 + (p - cum);
        pr[p] = (uint32_t)(a * ROWB) | ((uint32_t)(b * ROWB) << 16);
    }
    __syncthreads();

    // Bit-pack: task = (wg, colgroup of 4). 63*16 = 1008 tasks, 4 cols/thread.
    for (int task = tid; task < WG_PER_T * 16; task += 512) {
        int wg = task >> 4, cg = task & 15;
        const uint32_t* prp = &pr[wg << 5];
        const char* xb = (const char*)xs + cg * 16;
        uint32_t w0 = 0, w1 = 0, w2 = 0, w3 = 0;
        #pragma unroll
        for (int s = 0; s < 32; s++) {
            uint32_t u = prp[s];
            float4 fa = *(const float4*)(xb + (u & 0xFFFFu));
            float4 fb = *(const float4*)(xb + (u >> 16));
            w0 |= (fa.x > fb.x) ? (1u << s) : 0u;
            w1 |= (fa.y > fb.y) ? (1u << s) : 0u;
            w2 |= (fa.z > fb.z) ? (1u << s) : 0u;
            w3 |= (fa.w > fb.w) ? (1u << s) : 0u;
        }
        *(uint4*)&bits[wg][cg << 2] = make_uint4(w0, w1, w2, w3);
    }
    __syncthreads();

    // Gram: 136 upper-triangle 4x4 tiles, 16 accumulators, full 63-word sweep.
    if (tid < 136) {
        int ti = 0, rem = tid;
        while (rem >= 16 - ti) { rem -= 16 - ti; ti++; }
        int tj = ti + rem;
        int i0 = ti << 2, j0 = tj << 2;

        int acc[16];
        #pragma unroll
        for (int k = 0; k < 16; k++) acc[k] = 0;

        #pragma unroll 3
        for (int w = 0; w < WG_PER_T; w++) {
            uint4 bi = *(const uint4*)&bits[w][i0];
            uint4 bj = *(const uint4*)&bits[w][j0];
            uint32_t iv[4] = {bi.x, bi.y, bi.z, bi.w};
            uint32_t jv[4] = {bj.x, bj.y, bj.z, bj.w};
            #pragma unroll
            for (int ii = 0; ii < 4; ii++)
                #pragma unroll
                for (int jj = 0; jj < 4; jj++)
                    acc[ii * 4 + jj] += __popc(iv[ii] ^ jv[jj]);
        }
        #pragma unroll
        for (int k = 0; k < 16; k++) {
            int i = i0 + (k >> 2), j = j0 + (k & 3);
            if (i < j) atomicAdd(&g_H[i * NN + j], acc[k]);
        }
    }
}

// ---------------- distance + broadcast ----------------
// D[i,j] = 1 - C/2016, C = 1032192 - 4H (K = 516096 unordered samples), diag 0.
__global__ __launch_bounds__(256) void phase3(float* __restrict__ out) {
    __shared__ __align__(16) float D[NN * NN];
    int tid = threadIdx.x;
    for (int k = tid; k < NN * NN; k += 256) {
        int i = k >> 6, j = k & 63;
        float d = 0.0f;
        if (i != j) {
            int h = (i < j) ? g_H[i * NN + j] : g_H[j * NN + i];
            float C = 1032192.0f - 4.0f * (float)h;
            d = 1.0f - C * (1.0f / 2016.0f);
        }
        D[k] = d;
    }
    __syncthreads();
    float4* o = (float4*)(out + (size_t)blockIdx.x * (NN * NN));
    const float4* s = (const float4*)D;
    for (int k = tid; k < NN * NN / 4; k += 256) o[k] = s[k];
}

extern "C" void kernel_launch(void* const* d_in, const int* in_sizes, int n_in,
                              void* d_out, int out_size) {
    (void)in_sizes; (void)n_in; (void)out_size;
    const float* in = (const float*)d_in[0];
    float* out = (float*)d_out;

    zeroH<<<1, 512>>>();
    fusedKD<<<TT, 512>>>(in);
    phase3<<<BB, 256>>>(out);
}